// round 1
// baseline (speedup 1.0000x reference)
#include <cuda_runtime.h>
#include <math.h>
#include <math_constants.h>

#define NUM_CLASSES 200
#define NUM_PROTO   10
#define EMBED_D     512
#define NQ          8192
#define ITERS       5
#define EPSF        0.01f
#define INV_EPS     100.0f
#define EPS_LOG     1e-8f
#define MOM         0.02f
#define NCAP        1024   // smem capacity for per-class weight matrix (rows)

// ---------------- scratch (allocation-free: __device__ globals) ----------------
__device__ float g_tok[NQ * EMBED_D];        // normalized tokens, 16.8 MB
__device__ float g_S[NQ * NUM_PROTO];        // S[n][j] = <proto_{c(n)*10+j}, tok_n>
__device__ float g_v[NQ];                    // v, compacted per class
__device__ float g_wfall[NQ * NUM_PROTO];    // fallback weights if N_c > NCAP
__device__ int   g_counts[NUM_CLASSES];
__device__ int   g_off[NUM_CLASSES];
__device__ int   g_idx[NQ];                  // per-class token index lists
__device__ int   g_lab[NQ];                  // labels converted to int32

// ---------------- K1: detect label dtype, convert, histogram, scan -------------
__global__ void k_count(const void* labels_raw) {
    __shared__ int sc[NUM_CLASSES];
    __shared__ int s_is64;
    int t = threadIdx.x;
    if (t < NUM_CLASSES) sc[t] = 0;
    if (t < 32) {
        // If the buffer is really int64, all 32 first values are in [0,200).
        // If it's int32, the int64 interpretation packs two labels -> huge values.
        long long v = ((const long long*)labels_raw)[t];
        unsigned bal = __ballot_sync(0xffffffffu, v >= 0 && v < NUM_CLASSES);
        if (t == 0) s_is64 = (__popc(bal) >= 16) ? 1 : 0;
    }
    __syncthreads();
    const int is64 = s_is64;
    const long long* l64 = (const long long*)labels_raw;
    const int*       l32 = (const int*)labels_raw;
    for (int i = t; i < NQ; i += blockDim.x) {
        int lab = is64 ? (int)l64[i] : l32[i];
        g_lab[i] = lab;
        atomicAdd(&sc[lab], 1);
    }
    __syncthreads();
    if (t == 0) {
        int run = 0;
        for (int c = 0; c < NUM_CLASSES; c++) {
            g_off[c] = run;
            g_counts[c] = sc[c];
            run += sc[c];
        }
    }
}

// ---------------- K2: deterministic per-class index lists (1 warp / class) -----
__global__ void k_index() {
    int c = blockIdx.x;
    int lane = threadIdx.x;
    int base = g_off[c];
    for (int chunk = 0; chunk < NQ; chunk += 32) {
        int lab = g_lab[chunk + lane];
        bool m = (lab == c);
        unsigned bal = __ballot_sync(0xffffffffu, m);
        if (m) g_idx[base + __popc(bal & ((1u << lane) - 1u))] = chunk + lane;
        base += __popc(bal);
    }
}

__device__ __forceinline__ float dot4(float4 a, float4 b) {
    return a.x * b.x + a.y * b.y + a.z * b.z + a.w * b.w;
}
__device__ __forceinline__ float warp_sum(float v) {
    #pragma unroll
    for (int o = 16; o; o >>= 1) v += __shfl_xor_sync(0xffffffffu, v, o);
    return v;
}

// ---------------- K3: per class: normalize tokens + masked dots S ---------------
__global__ void __launch_bounds__(256, 4) k_prep(const float* __restrict__ tokens,
                                                 const float* __restrict__ protos) {
    __shared__ float sp[NUM_PROTO * EMBED_D];   // 20 KB: this class's prototypes
    int c = blockIdx.x;
    int n_c = g_counts[c];
    if (n_c == 0) return;
    for (int i = threadIdx.x; i < NUM_PROTO * EMBED_D; i += blockDim.x)
        sp[i] = protos[c * NUM_PROTO * EMBED_D + i];
    __syncthreads();

    int off  = g_off[c];
    int wid  = threadIdx.x >> 5;
    int lane = threadIdx.x & 31;
    for (int i = wid; i < n_c; i += 8) {
        int n = g_idx[off + i];
        const float4* tp = (const float4*)(tokens + (size_t)n * EMBED_D);
        float4 t0 = tp[lane], t1 = tp[lane + 32], t2 = tp[lane + 64], t3 = tp[lane + 96];
        float ss = dot4(t0, t0) + dot4(t1, t1) + dot4(t2, t2) + dot4(t3, t3);
        ss = warp_sum(ss);
        float inv = rsqrtf(ss);
        float4* gt = (float4*)(g_tok + (size_t)n * EMBED_D);
        float4 o0 = make_float4(t0.x*inv, t0.y*inv, t0.z*inv, t0.w*inv);
        float4 o1 = make_float4(t1.x*inv, t1.y*inv, t1.z*inv, t1.w*inv);
        float4 o2 = make_float4(t2.x*inv, t2.y*inv, t2.z*inv, t2.w*inv);
        float4 o3 = make_float4(t3.x*inv, t3.y*inv, t3.z*inv, t3.w*inv);
        gt[lane] = o0; gt[lane + 32] = o1; gt[lane + 64] = o2; gt[lane + 96] = o3;
        #pragma unroll
        for (int j = 0; j < NUM_PROTO; j++) {
            const float4* pp = (const float4*)(sp + j * EMBED_D);
            float d = dot4(t0, pp[lane]) + dot4(t1, pp[lane + 32]) +
                      dot4(t2, pp[lane + 64]) + dot4(t3, pp[lane + 96]);
            d = warp_sum(d);
            if (lane == 0) g_S[n * NUM_PROTO + j] = d * inv;
        }
    }
}

// ---------------- K4: per class: Sinkhorn + update + l2norm + writeout ----------
__global__ void __launch_bounds__(512, 2) k_sinkhorn(const float* __restrict__ protos,
                                                     float* __restrict__ out) {
    __shared__ float su[NUM_PROTO];
    __shared__ float ws_s[NCAP * NUM_PROTO];    // 40 KB transport weights
    __shared__ float red[16];
    __shared__ float tot_s;

    int c   = blockIdx.x;
    int n_c = g_counts[c];
    int tid = threadIdx.x;
    int wid = tid >> 5, lane = tid & 31;

    if (n_c == 0) {
        // out = l2norm(0.98 * proto) = proto (input is unit-norm)
        #pragma unroll
        for (int j = 0; j < NUM_PROTO; j++) {
            int r = c * NUM_PROTO + j;
            out[(size_t)r * EMBED_D + tid] = protos[(size_t)r * EMBED_D + tid];
        }
        return;
    }

    int off = g_off[c];
    for (int i = tid; i < n_c; i += 512) g_v[off + i] = 0.0f;
    __syncthreads();

    const float log_a = logf(1.0f / (float)NUM_PROTO + EPS_LOG);
    const float log_b = logf(1.0f / (float)n_c + EPS_LOG);

    for (int it = 0; it < ITERS; it++) {
        // --- u update: warp j does online LSE over this class's tokens ---
        if (wid < NUM_PROTO) {
            int j = wid;
            float m = -CUDART_INF_F, s = 0.0f;
            for (int i = lane; i < n_c; i += 32) {
                float a = g_S[g_idx[off + i] * NUM_PROTO + j] + g_v[off + i];
                if (a > m) { s = s * expf((m - a) * INV_EPS) + 1.0f; m = a; }
                else       { s += expf((a - m) * INV_EPS); }
            }
            #pragma unroll
            for (int o = 16; o; o >>= 1) {
                float mo = __shfl_xor_sync(0xffffffffu, m, o);
                float so = __shfl_xor_sync(0xffffffffu, s, o);
                float M = fmaxf(m, mo);
                if (M > -CUDART_INF_F) {
                    float s1 = (m  == -CUDART_INF_F) ? 0.0f : s  * expf((m  - M) * INV_EPS);
                    float s2 = (mo == -CUDART_INF_F) ? 0.0f : so * expf((mo - M) * INV_EPS);
                    s = s1 + s2; m = M;
                }
            }
            if (lane == 0) su[j] = EPSF * log_a - m - EPSF * logf(s);
        }
        __syncthreads();
        // --- v update: one thread per token ---
        for (int i = tid; i < n_c; i += 512) {
            int n = g_idx[off + i];
            float b[NUM_PROTO];
            float m = -CUDART_INF_F;
            #pragma unroll
            for (int j = 0; j < NUM_PROTO; j++) {
                b[j] = g_S[n * NUM_PROTO + j] + su[j];
                m = fmaxf(m, b[j]);
            }
            float s = 0.0f;
            #pragma unroll
            for (int j = 0; j < NUM_PROTO; j++) s += expf((b[j] - m) * INV_EPS);
            g_v[off + i] = EPSF * log_b - m - EPSF * logf(s);
        }
        __syncthreads();
    }

    // --- transport weights, column-normalized (pi_ columns sum to 1) ---
    float* ws = (n_c <= NCAP) ? ws_s : (g_wfall + (size_t)off * NUM_PROTO);
    for (int i = tid; i < n_c; i += 512) {
        int n = g_idx[off + i];
        float vv = g_v[off + i];
        float w[NUM_PROTO];
        float cs = 0.0f;
        #pragma unroll
        for (int j = 0; j < NUM_PROTO; j++) {
            w[j] = expf((g_S[n * NUM_PROTO + j] + su[j] + vv) * INV_EPS);
            cs += w[j];
        }
        float ics = 1.0f / cs;
        #pragma unroll
        for (int j = 0; j < NUM_PROTO; j++) ws[i * NUM_PROTO + j] = w[j] * ics;
    }
    __syncthreads();

    // --- new_protos = pi_ @ tok : thread owns dim d = tid ---
    int d = tid;
    float acc[NUM_PROTO];
    #pragma unroll
    for (int j = 0; j < NUM_PROTO; j++) acc[j] = 0.0f;
    for (int i = 0; i < n_c; i++) {
        float t = g_tok[(size_t)g_idx[off + i] * EMBED_D + d];
        #pragma unroll
        for (int j = 0; j < NUM_PROTO; j++) acc[j] += ws[i * NUM_PROTO + j] * t;
    }

    // --- momentum blend + per-row l2norm + writeout ---
    float r[NUM_PROTO];
    #pragma unroll
    for (int j = 0; j < NUM_PROTO; j++)
        r[j] = (1.0f - MOM) * protos[(size_t)(c * NUM_PROTO + j) * EMBED_D + d] + MOM * acc[j];

    for (int j = 0; j < NUM_PROTO; j++) {
        float x = warp_sum(r[j] * r[j]);
        if (lane == 0) red[wid] = x;
        __syncthreads();
        if (tid < 16) {
            float y = red[tid];
            #pragma unroll
            for (int o = 8; o; o >>= 1) y += __shfl_xor_sync(0x0000ffffu, y, o);
            if (tid == 0) tot_s = y;
        }
        __syncthreads();
        float inv = rsqrtf(tot_s);
        out[(size_t)(c * NUM_PROTO + j) * EMBED_D + d] = r[j] * inv;
        __syncthreads();
    }
}

// -------------------------------- launch ---------------------------------------
extern "C" void kernel_launch(void* const* d_in, const int* in_sizes, int n_in,
                              void* d_out, int out_size) {
    const float* tokens = (const float*)d_in[0];
    const void*  labels = d_in[1];
    const float* protos = (const float*)d_in[2];
    float* out = (float*)d_out;

    k_count<<<1, 256>>>(labels);
    k_index<<<NUM_CLASSES, 32>>>();
    k_prep<<<NUM_CLASSES, 256>>>(tokens, protos);
    k_sinkhorn<<<NUM_CLASSES, 512>>>(protos, out);
}

// round 2
// speedup vs baseline: 1.1196x; 1.1196x over previous
#include <cuda_runtime.h>
#include <math.h>
#include <math_constants.h>

#define NUM_CLASSES 200
#define NUM_PROTO   10
#define EMBED_D     512
#define NQ          8192
#define ITERS       5
#define EPSF        0.01f
#define INV_EPS     100.0f
#define EPS_LOG     1e-8f
#define MOM         0.02f
#define NCAP        512    // smem row capacity per class (mean n_c ~41; 512 = >12 sigma)

// ---------------- scratch (allocation-free: __device__ globals) ----------------
__device__ int   g_counts[NUM_CLASSES];
__device__ int   g_off[NUM_CLASSES];
__device__ int   g_idx[NQ];                  // per-class token index lists
__device__ int   g_lab[NQ];                  // labels converted to int32
// fallback scratch (only used if a class exceeds NCAP rows)
__device__ float g_Sf[NQ * NUM_PROTO];
__device__ float g_vf[NQ];
__device__ float g_if[NQ];

// ---------------- K1: detect label dtype, convert, histogram, scan -------------
__global__ void k_count(const void* labels_raw) {
    __shared__ int sc[NUM_CLASSES];
    __shared__ int s_is64;
    int t = threadIdx.x;
    if (t < NUM_CLASSES) sc[t] = 0;
    if (t < 32) {
        long long v = ((const long long*)labels_raw)[t];
        unsigned bal = __ballot_sync(0xffffffffu, v >= 0 && v < NUM_CLASSES);
        if (t == 0) s_is64 = (__popc(bal) >= 16) ? 1 : 0;
    }
    __syncthreads();
    const int is64 = s_is64;
    const long long* l64 = (const long long*)labels_raw;
    const int*       l32 = (const int*)labels_raw;
    for (int i = t; i < NQ; i += blockDim.x) {
        int lab = is64 ? (int)l64[i] : l32[i];
        g_lab[i] = lab;
        atomicAdd(&sc[lab], 1);
    }
    __syncthreads();
    if (t == 0) {
        int run = 0;
        for (int c = 0; c < NUM_CLASSES; c++) {
            g_off[c] = run;
            g_counts[c] = sc[c];
            run += sc[c];
        }
    }
}

// ---------------- K2: deterministic per-class index lists (1 warp / class) -----
__global__ void k_index() {
    int c = blockIdx.x;
    int lane = threadIdx.x;
    int base = g_off[c];
    #pragma unroll 4
    for (int chunk = 0; chunk < NQ; chunk += 32) {
        int lab = g_lab[chunk + lane];
        bool m = (lab == c);
        unsigned bal = __ballot_sync(0xffffffffu, m);
        if (m) g_idx[base + __popc(bal & ((1u << lane) - 1u))] = chunk + lane;
        base += __popc(bal);
    }
}

__device__ __forceinline__ float dot4(float4 a, float4 b) {
    return a.x * b.x + a.y * b.y + a.z * b.z + a.w * b.w;
}
__device__ __forceinline__ float warp_sum(float v) {
    #pragma unroll
    for (int o = 16; o; o >>= 1) v += __shfl_xor_sync(0xffffffffu, v, o);
    return v;
}

// ---------------- fused per-class body (S/V/IV may be smem or global) ----------
template<bool SM>
__device__ __forceinline__ void class_body(
    int c, int n_c, int off,
    const float* __restrict__ tokens, const float* __restrict__ protos,
    float* __restrict__ out,
    float* sp,            // [10*512] smem prototypes
    int*   sidx,          // [NCAP or n/a] smem indices (SM path), else g_idx+off
    float* S, float* V, float* IV,
    float* su, float* red, float* tot_s)
{
    int tid = threadIdx.x;
    int wid = tid >> 5, lane = tid & 31;

    // stage protos + indices, zero v
    for (int i = tid; i < NUM_PROTO * EMBED_D; i += 512)
        sp[i] = protos[(size_t)c * NUM_PROTO * EMBED_D + i];
    const int* IDX;
    if (SM) {
        for (int i = tid; i < n_c; i += 512) sidx[i] = g_idx[off + i];
        IDX = sidx;
    } else {
        IDX = g_idx + off;
    }
    for (int i = tid; i < n_c; i += 512) V[i] = 0.0f;
    __syncthreads();

    // --- phase A: per-row norm + 10 masked dots (warp per row) ---
    for (int i = wid; i < n_c; i += 16) {
        int n = IDX[i];
        const float4* tp = (const float4*)(tokens + (size_t)n * EMBED_D);
        float4 t0 = tp[lane], t1 = tp[lane + 32], t2 = tp[lane + 64], t3 = tp[lane + 96];
        float ss = dot4(t0, t0) + dot4(t1, t1) + dot4(t2, t2) + dot4(t3, t3);
        ss = warp_sum(ss);
        float inv = rsqrtf(ss);
        if (lane == 0) IV[i] = inv;
        #pragma unroll
        for (int j = 0; j < NUM_PROTO; j++) {
            const float4* pp = (const float4*)(sp + j * EMBED_D);
            float d = dot4(t0, pp[lane]) + dot4(t1, pp[lane + 32]) +
                      dot4(t2, pp[lane + 64]) + dot4(t3, pp[lane + 96]);
            d = warp_sum(d);
            if (lane == 0) S[i * NUM_PROTO + j] = d * inv;
        }
    }
    __syncthreads();

    // --- phase B: 5 Sinkhorn iterations entirely on S/V (smem) ---
    const float log_a = logf(1.0f / (float)NUM_PROTO + EPS_LOG);
    const float log_b = logf(1.0f / (float)n_c + EPS_LOG);
    for (int it = 0; it < ITERS; it++) {
        if (wid < NUM_PROTO) {              // u update: warp j -> online LSE over rows
            int j = wid;
            float m = -CUDART_INF_F, s = 0.0f;
            for (int i = lane; i < n_c; i += 32) {
                float a = S[i * NUM_PROTO + j] + V[i];
                if (a > m) { s = s * expf((m - a) * INV_EPS) + 1.0f; m = a; }
                else       { s += expf((a - m) * INV_EPS); }
            }
            #pragma unroll
            for (int o = 16; o; o >>= 1) {
                float mo = __shfl_xor_sync(0xffffffffu, m, o);
                float so = __shfl_xor_sync(0xffffffffu, s, o);
                float M = fmaxf(m, mo);
                if (M > -CUDART_INF_F) {
                    float s1 = (m  == -CUDART_INF_F) ? 0.0f : s  * expf((m  - M) * INV_EPS);
                    float s2 = (mo == -CUDART_INF_F) ? 0.0f : so * expf((mo - M) * INV_EPS);
                    s = s1 + s2; m = M;
                }
            }
            if (lane == 0) su[j] = EPSF * log_a - m - EPSF * logf(s);
        }
        __syncthreads();
        for (int i = tid; i < n_c; i += 512) {   // v update: thread per row
            float b[NUM_PROTO];
            float m = -CUDART_INF_F;
            #pragma unroll
            for (int j = 0; j < NUM_PROTO; j++) {
                b[j] = S[i * NUM_PROTO + j] + su[j];
                m = fmaxf(m, b[j]);
            }
            float s = 0.0f;
            #pragma unroll
            for (int j = 0; j < NUM_PROTO; j++) s += expf((b[j] - m) * INV_EPS);
            V[i] = EPSF * log_b - m - EPSF * logf(s);
        }
        __syncthreads();
    }

    // --- phase C: column-normalized transport weights * inv-norm, in place ---
    for (int i = tid; i < n_c; i += 512) {
        float vv = V[i];
        float w[NUM_PROTO];
        float cs = 0.0f;
        #pragma unroll
        for (int j = 0; j < NUM_PROTO; j++) {
            w[j] = expf((S[i * NUM_PROTO + j] + su[j] + vv) * INV_EPS);
            cs += w[j];
        }
        float scale = IV[i] / cs;   // fold 1/||tok|| so phase D uses raw tokens
        #pragma unroll
        for (int j = 0; j < NUM_PROTO; j++) S[i * NUM_PROTO + j] = w[j] * scale;
    }
    __syncthreads();

    // --- phase D: new_protos = weights^T @ raw_tokens (thread owns dim d) ---
    int d = tid;
    float acc[NUM_PROTO];
    #pragma unroll
    for (int j = 0; j < NUM_PROTO; j++) acc[j] = 0.0f;
    #pragma unroll 4
    for (int i = 0; i < n_c; i++) {
        float t = __ldg(tokens + (size_t)IDX[i] * EMBED_D + d);   // L1 hit (phase A warmed)
        #pragma unroll
        for (int j = 0; j < NUM_PROTO; j++) acc[j] += S[i * NUM_PROTO + j] * t;
    }

    // --- phase E: momentum blend + per-row l2norm + writeout ---
    float r[NUM_PROTO];
    #pragma unroll
    for (int j = 0; j < NUM_PROTO; j++)
        r[j] = (1.0f - MOM) * sp[j * EMBED_D + d] + MOM * acc[j];

    for (int j = 0; j < NUM_PROTO; j++) {
        float x = warp_sum(r[j] * r[j]);
        if (lane == 0) red[wid] = x;
        __syncthreads();
        if (tid < 16) {
            float y = red[tid];
            #pragma unroll
            for (int o = 8; o; o >>= 1) y += __shfl_xor_sync(0x0000ffffu, y, o);
            if (tid == 0) *tot_s = y;
        }
        __syncthreads();
        float inv = rsqrtf(*tot_s);
        out[(size_t)(c * NUM_PROTO + j) * EMBED_D + d] = r[j] * inv;
        __syncthreads();
    }
}

// ---------------- K3: fused per-class kernel -----------------------------------
__global__ void __launch_bounds__(512, 2) k_main(const float* __restrict__ tokens,
                                                 const float* __restrict__ protos,
                                                 float* __restrict__ out) {
    __shared__ float sp[NUM_PROTO * EMBED_D];     // 20 KB
    __shared__ float ssS[NCAP * NUM_PROTO];       // 20 KB
    __shared__ float ssV[NCAP];                   //  2 KB
    __shared__ float ssI[NCAP];                   //  2 KB
    __shared__ int   sidx[NCAP];                  //  2 KB
    __shared__ float su[NUM_PROTO];
    __shared__ float red[16];
    __shared__ float tot_s;

    int c   = blockIdx.x;
    int n_c = g_counts[c];
    int tid = threadIdx.x;

    if (n_c == 0) {   // out = l2norm(0.98*proto) = proto (unit-norm input)
        #pragma unroll
        for (int j = 0; j < NUM_PROTO; j++) {
            size_t r = (size_t)(c * NUM_PROTO + j) * EMBED_D + tid;
            out[r] = protos[r];
        }
        return;
    }
    int off = g_off[c];
    if (n_c <= NCAP) {
        class_body<true >(c, n_c, off, tokens, protos, out, sp, sidx,
                          ssS, ssV, ssI, su, red, &tot_s);
    } else {          // statistically unreachable; correct fallback via global scratch
        class_body<false>(c, n_c, off, tokens, protos, out, sp, sidx,
                          g_Sf + (size_t)off * NUM_PROTO, g_vf + off, g_if + off,
                          su, red, &tot_s);
    }
}

// -------------------------------- launch ---------------------------------------
extern "C" void kernel_launch(void* const* d_in, const int* in_sizes, int n_in,
                              void* d_out, int out_size) {
    const float* tokens = (const float*)d_in[0];
    const void*  labels = d_in[1];
    const float* protos = (const float*)d_in[2];
    float* out = (float*)d_out;

    k_count<<<1, 256>>>(labels);
    k_index<<<NUM_CLASSES, 32>>>();
    k_main<<<NUM_CLASSES, 512>>>(tokens, protos, out);
}

// round 3
// speedup vs baseline: 3.0067x; 2.6855x over previous
#include <cuda_runtime.h>
#include <math.h>
#include <math_constants.h>

#define NUM_CLASSES 200
#define NUM_PROTO   10
#define EMBED_D     512
#define NQ          8192
#define NCHUNK      (NQ / 32)     // 256 label chunks of 32
#define ITERS       5
#define EPSF        0.01f
#define INV_EPS     100.0f
#define EPS_LOG     1e-8f
#define MOM         0.02f
#define NCAP        192           // smem row capacity (mean n_c ~41, sd 6.4)

// ---------------- scratch (allocation-free: __device__ globals) ----------------
__device__ int   g_lab[NQ];                  // labels converted to int32
// fallback scratch for the (statistically unreachable) n_c > NCAP case,
// indexed by off = #(labels < c) -> disjoint regions per class
__device__ int   g_fidx[NQ];
__device__ float g_Sf[NQ * NUM_PROTO];
__device__ float g_vf[NQ];
__device__ float g_if[NQ];

// ---------------- K1: detect label dtype, convert to int32 --------------------
__global__ void k_lab(const void* labels_raw) {
    __shared__ int s_is64;
    int tid = threadIdx.x;
    if (tid < 32) {
        // int64 interpretation of first 32 values in [0,200) -> really int64.
        long long v = ((const long long*)labels_raw)[tid];
        unsigned bal = __ballot_sync(0xffffffffu, v >= 0 && v < NUM_CLASSES);
        if (tid == 0) s_is64 = (__popc(bal) >= 16) ? 1 : 0;
    }
    __syncthreads();
    int i = blockIdx.x * blockDim.x + tid;
    if (i < NQ) {
        g_lab[i] = s_is64 ? (int)((const long long*)labels_raw)[i]
                          : ((const int*)labels_raw)[i];
    }
}

__device__ __forceinline__ float dot4(float4 a, float4 b) {
    return a.x * b.x + a.y * b.y + a.z * b.z + a.w * b.w;
}
__device__ __forceinline__ float warp_sum(float v) {
    #pragma unroll
    for (int o = 16; o; o >>= 1) v += __shfl_xor_sync(0xffffffffu, v, o);
    return v;
}

// ---------------- fused per-class body (state in smem or global fallback) ------
template<bool SM>
__device__ __forceinline__ void class_body(
    int c, int n_c,
    const float* __restrict__ tokens,
    float* __restrict__ out,
    const float* sp,                   // [10*512] smem prototypes (already staged)
    const int* IDX, float* S, float* V, float* IV,
    float* su, float* red, float* sinv)
{
    int tid = threadIdx.x;
    int wid = tid >> 5, lane = tid & 31;

    for (int i = tid; i < n_c; i += 512) V[i] = 0.0f;
    __syncthreads();

    // --- phase A: per-row norm + 10 masked dots (warp per row) ---
    for (int i = wid; i < n_c; i += 16) {
        int n = IDX[i];
        const float4* tp = (const float4*)(tokens + (size_t)n * EMBED_D);
        float4 t0 = tp[lane], t1 = tp[lane + 32], t2 = tp[lane + 64], t3 = tp[lane + 96];
        float ss = dot4(t0, t0) + dot4(t1, t1) + dot4(t2, t2) + dot4(t3, t3);
        ss = warp_sum(ss);
        float inv = rsqrtf(ss);
        if (lane == 0) IV[i] = inv;
        #pragma unroll
        for (int j = 0; j < NUM_PROTO; j++) {
            const float4* pp = (const float4*)(sp + j * EMBED_D);
            float d = dot4(t0, pp[lane]) + dot4(t1, pp[lane + 32]) +
                      dot4(t2, pp[lane + 64]) + dot4(t3, pp[lane + 96]);
            d = warp_sum(d);
            if (lane == 0) S[i * NUM_PROTO + j] = d * inv;
        }
    }
    __syncthreads();

    // --- phase B: 5 Sinkhorn iterations on S/V ---
    const float log_a = logf(1.0f / (float)NUM_PROTO + EPS_LOG);
    const float log_b = logf(1.0f / (float)n_c + EPS_LOG);
    for (int it = 0; it < ITERS; it++) {
        if (wid < NUM_PROTO) {              // u update: warp j -> online LSE over rows
            int j = wid;
            float m = -CUDART_INF_F, s = 0.0f;
            for (int i = lane; i < n_c; i += 32) {
                float a = S[i * NUM_PROTO + j] + V[i];
                if (a > m) { s = s * expf((m - a) * INV_EPS) + 1.0f; m = a; }
                else       { s += expf((a - m) * INV_EPS); }
            }
            #pragma unroll
            for (int o = 16; o; o >>= 1) {
                float mo = __shfl_xor_sync(0xffffffffu, m, o);
                float so = __shfl_xor_sync(0xffffffffu, s, o);
                float M = fmaxf(m, mo);
                if (M > -CUDART_INF_F) {
                    float s1 = (m  == -CUDART_INF_F) ? 0.0f : s  * expf((m  - M) * INV_EPS);
                    float s2 = (mo == -CUDART_INF_F) ? 0.0f : so * expf((mo - M) * INV_EPS);
                    s = s1 + s2; m = M;
                }
            }
            if (lane == 0) su[j] = EPSF * log_a - m - EPSF * logf(s);
        }
        __syncthreads();
        for (int i = tid; i < n_c; i += 512) {   // v update: thread per row
            float b[NUM_PROTO];
            float m = -CUDART_INF_F;
            #pragma unroll
            for (int j = 0; j < NUM_PROTO; j++) {
                b[j] = S[i * NUM_PROTO + j] + su[j];
                m = fmaxf(m, b[j]);
            }
            float s = 0.0f;
            #pragma unroll
            for (int j = 0; j < NUM_PROTO; j++) s += expf((b[j] - m) * INV_EPS);
            V[i] = EPSF * log_b - m - EPSF * logf(s);
        }
        __syncthreads();
    }

    // --- phase C: column-normalized transport weights * inv-norm, in place ---
    for (int i = tid; i < n_c; i += 512) {
        float vv = V[i];
        float w[NUM_PROTO];
        float cs = 0.0f;
        #pragma unroll
        for (int j = 0; j < NUM_PROTO; j++) {
            w[j] = expf((S[i * NUM_PROTO + j] + su[j] + vv) * INV_EPS);
            cs += w[j];
        }
        float scale = IV[i] / cs;     // fold 1/||tok|| so phase D uses raw tokens
        #pragma unroll
        for (int j = 0; j < NUM_PROTO; j++) S[i * NUM_PROTO + j] = w[j] * scale;
    }
    __syncthreads();

    // --- phase D: new_protos = weights^T @ raw_tokens (thread owns dim d) ---
    int d = tid;
    float acc[NUM_PROTO];
    #pragma unroll
    for (int j = 0; j < NUM_PROTO; j++) acc[j] = 0.0f;
    #pragma unroll 4
    for (int i = 0; i < n_c; i++) {
        float t = __ldg(tokens + (size_t)IDX[i] * EMBED_D + d);  // L1-warm from phase A
        #pragma unroll
        for (int j = 0; j < NUM_PROTO; j++) acc[j] += S[i * NUM_PROTO + j] * t;
    }

    // --- phase E: momentum blend + batched per-row l2norm + writeout ---
    float r[NUM_PROTO];
    #pragma unroll
    for (int j = 0; j < NUM_PROTO; j++) {
        r[j] = (1.0f - MOM) * sp[j * EMBED_D + d] + MOM * acc[j];
        float x = warp_sum(r[j] * r[j]);
        if (lane == 0) red[wid * NUM_PROTO + j] = x;
    }
    __syncthreads();
    if (wid < NUM_PROTO) {
        int j = wid;
        float y = (lane < 16) ? red[lane * NUM_PROTO + j] : 0.0f;
        y = warp_sum(y);
        if (lane == 0) sinv[j] = rsqrtf(y);
    }
    __syncthreads();
    #pragma unroll
    for (int j = 0; j < NUM_PROTO; j++)
        out[(size_t)(c * NUM_PROTO + j) * EMBED_D + d] = r[j] * sinv[j];
}

// ---------------- K2: fully fused per-class kernel -----------------------------
__global__ void __launch_bounds__(512) k_main(const float* __restrict__ tokens,
                                              const float* __restrict__ protos,
                                              float* __restrict__ out) {
    __shared__ float sp[NUM_PROTO * EMBED_D];     // 20 KB
    __shared__ float ssS[NCAP * NUM_PROTO];       // 7.5 KB
    __shared__ float ssV[NCAP];
    __shared__ float ssI[NCAP];
    __shared__ int   sidx[NCAP];
    __shared__ int   ccnt[NCHUNK];                // per-chunk match counts -> offsets
    __shared__ float su[NUM_PROTO];
    __shared__ float red[16 * NUM_PROTO];
    __shared__ float sinv[NUM_PROTO];
    __shared__ int   s_n, s_lt;

    int c    = blockIdx.x;
    int tid  = threadIdx.x;
    int wid  = tid >> 5, lane = tid & 31;

    // stage prototypes early (overlaps with label scan)
    for (int i = tid; i < NUM_PROTO * EMBED_D; i += 512)
        sp[i] = protos[(size_t)c * NUM_PROTO * EMBED_D + i];
    if (tid == 0) s_lt = 0;
    __syncthreads();

    // --- pass 1: per-chunk counts + count of labels < c (fallback offset) ---
    int lt_local = 0;
    #pragma unroll
    for (int k = 0; k < NCHUNK / 16; k++) {       // 16 chunks per warp
        int chunk = wid * (NCHUNK / 16) + k;
        int lab = g_lab[chunk * 32 + lane];
        unsigned bm = __ballot_sync(0xffffffffu, lab == c);
        unsigned bl = __ballot_sync(0xffffffffu, lab <  c);
        if (lane == 0) { ccnt[chunk] = __popc(bm); lt_local += __popc(bl); }
    }
    if (lane == 0 && lt_local) atomicAdd(&s_lt, lt_local);  // int atomics: deterministic
    __syncthreads();

    // --- exclusive prefix over 256 chunk counts (warp 0, serial groups) ---
    if (wid == 0) {
        int base = 0;
        #pragma unroll
        for (int g = 0; g < NCHUNK / 32; g++) {
            int v = ccnt[g * 32 + lane];
            int inc = v;
            #pragma unroll
            for (int o = 1; o < 32; o <<= 1) {
                int t = __shfl_up_sync(0xffffffffu, inc, o);
                if (lane >= o) inc += t;
            }
            ccnt[g * 32 + lane] = base + inc - v;           // exclusive
            base += __shfl_sync(0xffffffffu, inc, 31);
        }
        if (lane == 0) s_n = base;
    }
    __syncthreads();

    int n_c = s_n;
    if (n_c == 0) {   // out = l2norm(0.98*proto) = proto (unit-norm input)
        #pragma unroll
        for (int j = 0; j < NUM_PROTO; j++)
            out[(size_t)(c * NUM_PROTO + j) * EMBED_D + tid] = sp[j * EMBED_D + tid];
        return;
    }
    bool sm  = (n_c <= NCAP);
    int  off = s_lt;                               // compact offset for fallback

    // --- pass 2: ballot-rank compaction into index list (order-preserving) ---
    #pragma unroll
    for (int k = 0; k < NCHUNK / 16; k++) {
        int chunk = wid * (NCHUNK / 16) + k;
        int n = chunk * 32 + lane;
        int lab = g_lab[n];                        // L1 hit
        unsigned bm = __ballot_sync(0xffffffffu, lab == c);
        if (lab == c) {
            int pos = ccnt[chunk] + __popc(bm & ((1u << lane) - 1u));
            if (sm) sidx[pos] = n; else g_fidx[off + pos] = n;
        }
    }
    __syncthreads();

    if (sm) {
        class_body<true >(c, n_c, tokens, out, sp, sidx,
                          ssS, ssV, ssI, su, red, sinv);
    } else {
        class_body<false>(c, n_c, tokens, out, sp, g_fidx + off,
                          g_Sf + (size_t)off * NUM_PROTO, g_vf + off, g_if + off,
                          su, red, sinv);
    }
}

// -------------------------------- launch ---------------------------------------
extern "C" void kernel_launch(void* const* d_in, const int* in_sizes, int n_in,
                              void* d_out, int out_size) {
    const float* tokens = (const float*)d_in[0];
    const void*  labels = d_in[1];
    const float* protos = (const float*)d_in[2];
    float* out = (float*)d_out;

    k_lab<<<NQ / 1024, 1024>>>(labels);
    k_main<<<NUM_CLASSES, 512>>>(tokens, protos, out);
}